// round 13
// baseline (speedup 1.0000x reference)
#include <cuda_runtime.h>
#include <cuda_bf16.h>
#include <cstdint>

#define BATCH   2048
#define FLAT_IN 512
#define PROJ    256
#define HEADS   16384
#define ACT     64
#define NBLK    (HEADS / 16)          // 1024 16-head groups per row
#define CAND    64

// ---------------- scratch (__device__ globals; allocs are forbidden) -------
__device__ float   g_s[BATCH * PROJ];          // projected state fp32
__device__ int8_t  g_s_i8[BATCH * PROJ];       // s quantized (scale 1)
__device__ int8_t  g_mem_i8[HEADS * PROJ];     // mem quantized (scale 24)
__device__ float   g_blockmax[BATCH * NBLK];   // per-row per-16-head max (sim units)

// ---------------- helpers ---------------------------------------------------
__device__ __forceinline__ uint32_t smem_u32(const void* p) {
    uint32_t a;
    asm("{ .reg .u64 t; cvta.to.shared.u64 t, %1; cvt.u32.u64 %0, t; }"
        : "=r"(a) : "l"(p));
    return a;
}
__device__ __forceinline__ unsigned okey(float f) {
    unsigned u = __float_as_uint(f);
    return (u & 0x80000000u) ? ~u : (u | 0x80000000u);
}
__device__ __forceinline__ void ffma2(unsigned long long& d,
                                      unsigned long long a,
                                      unsigned long long b) {
    asm("fma.rn.f32x2 %0, %1, %2, %0;" : "+l"(d) : "l"(a), "l"(b));
}
__device__ __forceinline__ unsigned long long pack2(float x) {
    unsigned long long r;
    asm("mov.b64 %0, {%1, %1};" : "=l"(r) : "f"(x));
    return r;
}
__device__ __forceinline__ int s8c(float x) {
    int v = __float2int_rn(x);
    return v < -127 ? -127 : (v > 127 ? 127 : v);
}
__device__ __forceinline__ uint32_t pack4_s8(float a, float b, float c, float d,
                                             float sc) {
    int v0 = s8c(a * sc), v1 = s8c(b * sc), v2 = s8c(c * sc), v3 = s8c(d * sc);
    return (v0 & 0xFF) | ((v1 & 0xFF) << 8) | ((v2 & 0xFF) << 16) | (v3 << 24);
}

#define LDSM4(d, addr)                                                         \
    asm volatile("ldmatrix.sync.aligned.m8n8.x4.shared.b16 {%0,%1,%2,%3}, [%4];" \
        : "=r"((d)[0]), "=r"((d)[1]), "=r"((d)[2]), "=r"((d)[3]) : "r"(addr))

#define MMA_S8(c, a, br0, br1)                                                 \
    asm volatile("mma.sync.aligned.m16n8k32.row.col.s32.s8.s8.s32 "            \
        "{%0,%1,%2,%3}, {%4,%5,%6,%7}, {%8,%9}, {%0,%1,%2,%3};"                \
        : "+r"((c)[0]), "+r"((c)[1]), "+r"((c)[2]), "+r"((c)[3])               \
        : "r"((a)[0]), "r"((a)[1]), "r"((a)[2]), "r"((a)[3]),                  \
          "r"(br0), "r"(br1))

// ---------------------------------------------------------------------------
// K0: memories fp32 -> int8 (scale 24)   (8 elems / thread)
// ---------------------------------------------------------------------------
__global__ __launch_bounds__(256) void conv_mem_kernel(const float* __restrict__ mem) {
    size_t i = ((size_t)blockIdx.x * 256 + threadIdx.x) * 8;
    float4 a = *(const float4*)&mem[i];
    float4 b = *(const float4*)&mem[i + 4];
    uint2 u;
    u.x = pack4_s8(a.x, a.y, a.z, a.w, 24.0f);
    u.y = pack4_s8(b.x, b.y, b.z, b.w, 24.0f);
    *(uint2*)&g_mem_i8[i] = u;
}

// ---------------------------------------------------------------------------
// K1: s = state @ rp, fp32 (packed f32x2 FFMA); writes fp32 + int8(scale 1)
// ---------------------------------------------------------------------------
__global__ __launch_bounds__(256) void proj_kernel(const float* __restrict__ state,
                                                   const float* __restrict__ rp) {
    __shared__ __align__(16) float As[64 * 36];
    __shared__ __align__(16) float Bs[32 * 68];
    const int tid = threadIdx.x;
    const int tx = tid & 15, ty = tid >> 4;
    const int n0 = blockIdx.x * 64;
    const int b0 = blockIdx.y * 64;

    unsigned long long acc01[4], acc23[4];
    #pragma unroll
    for (int i = 0; i < 4; i++) { acc01[i] = 0ull; acc23[i] = 0ull; }

    for (int kt = 0; kt < FLAT_IN; kt += 32) {
        #pragma unroll
        for (int p = 0; p < 2; p++) {
            int idx = p * 256 + tid;
            int r = idx >> 3, c4 = idx & 7;
            *(float4*)&As[r * 36 + c4 * 4] =
                *(const float4*)&state[(size_t)(b0 + r) * FLAT_IN + kt + c4 * 4];
        }
        #pragma unroll
        for (int p = 0; p < 2; p++) {
            int idx = p * 256 + tid;
            int r = idx >> 4, c4 = idx & 15;
            *(float4*)&Bs[r * 68 + c4 * 4] =
                *(const float4*)&rp[(size_t)(kt + r) * PROJ + n0 + c4 * 4];
        }
        __syncthreads();
        #pragma unroll
        for (int k = 0; k < 32; k++) {
            ulonglong2 bp = *(const ulonglong2*)&Bs[k * 68 + tx * 4];
            #pragma unroll
            for (int i = 0; i < 4; i++) {
                unsigned long long aa = pack2(As[(ty * 4 + i) * 36 + k]);
                ffma2(acc01[i], aa, bp.x);
                ffma2(acc23[i], aa, bp.y);
            }
        }
        __syncthreads();
    }
    #pragma unroll
    for (int i = 0; i < 4; i++) {
        float c0, c1, c2, c3;
        asm("mov.b64 {%0, %1}, %2;" : "=f"(c0), "=f"(c1) : "l"(acc01[i]));
        asm("mov.b64 {%0, %1}, %2;" : "=f"(c2), "=f"(c3) : "l"(acc23[i]));
        size_t o = (size_t)(b0 + ty * 4 + i) * PROJ + n0 + tx * 4;
        *(float4*)&g_s[o] = make_float4(c0, c1, c2, c3);
        *(uint32_t*)&g_s_i8[o] = pack4_s8(c0, c1, c2, c3, 1.0f);
    }
}

// ---------------------------------------------------------------------------
// K2: S = s_i8 @ mem_i8^T via IMMA m16n8k32 s8 (exact s32 accum).
//     R7-certified mainloop; NEW epilogue: per-(row, 16-head) fp32 maxima
//     (register/shuffle reduce, no per-head array, no caps).
// ---------------------------------------------------------------------------
__global__ __launch_bounds__(256) void sim_mma_kernel() {
    __shared__ __align__(16) char As[2][128 * 80];   // 20KB
    __shared__ __align__(16) char Bs[2][128 * 80];   // 20KB
    __shared__ float sbm[128][8];                    // 4KB: [row][wn*4 + grp]

    const int tid  = threadIdx.x;
    const int lane = tid & 31, wid = tid >> 5;
    const int wm = wid & 3, wn = wid >> 2;
    const int h0 = blockIdx.x * 128, b0 = blockIdx.y * 128;

    const char* Ag = (const char*)g_s_i8   + (size_t)b0 * PROJ;
    const char* Bg = (const char*)g_mem_i8 + (size_t)h0 * PROJ;

    uint4 ra[2], rb[2];
    #define GLOAD(kt)                                                          \
        {                                                                      \
            _Pragma("unroll")                                                  \
            for (int p = 0; p < 2; p++) {                                      \
                int idx = p * 256 + tid;                                       \
                int r = idx >> 2, c = idx & 3;                                 \
                ra[p] = *(const uint4*)(Ag + (size_t)r * PROJ + (kt) * 64 + c * 16); \
                rb[p] = *(const uint4*)(Bg + (size_t)r * PROJ + (kt) * 64 + c * 16); \
            }                                                                  \
        }

    int acc[2][8][4];
    #pragma unroll
    for (int mt = 0; mt < 2; mt++)
        #pragma unroll
        for (int nt = 0; nt < 8; nt++)
            #pragma unroll
            for (int q = 0; q < 4; q++) acc[mt][nt][q] = 0;

    const uint32_t a_smem = smem_u32(As);
    const uint32_t b_smem = smem_u32(Bs);
    const uint32_t a_row = wm * 32 + (lane & 7) + ((lane >> 3) & 1) * 8;
    const uint32_t a_cb  = (lane >> 4) * 16;
    const uint32_t b_row = wn * 64 + (lane & 7) + (lane >> 4) * 8;
    const uint32_t b_cb  = ((lane >> 3) & 1) * 16;

    GLOAD(0);
    int buf = 0;
    #pragma unroll
    for (int kt = 0; kt < PROJ / 64; kt++) {
        #pragma unroll
        for (int p = 0; p < 2; p++) {
            int idx = p * 256 + tid;
            int r = idx >> 2, c = idx & 3;
            *(uint4*)&As[buf][r * 80 + c * 16] = ra[p];
            *(uint4*)&Bs[buf][r * 80 + c * 16] = rb[p];
        }
        __syncthreads();
        if (kt + 1 < PROJ / 64) GLOAD(kt + 1);

        const uint32_t ab = a_smem + (uint32_t)buf * (128 * 80);
        const uint32_t bb = b_smem + (uint32_t)buf * (128 * 80);
        #pragma unroll
        for (int ks = 0; ks < 2; ks++) {
            uint32_t af[2][4], bf[4][4];
            #pragma unroll
            for (int mt = 0; mt < 2; mt++)
                LDSM4(af[mt], ab + (a_row + mt * 16) * 80 + ks * 32 + a_cb);
            #pragma unroll
            for (int np = 0; np < 4; np++)
                LDSM4(bf[np], bb + (b_row + np * 16) * 80 + ks * 32 + b_cb);
            #pragma unroll
            for (int mt = 0; mt < 2; mt++)
                #pragma unroll
                for (int nt = 0; nt < 8; nt++)
                    MMA_S8(acc[mt][nt], af[mt],
                           bf[nt >> 1][(nt & 1) * 2], bf[nt >> 1][(nt & 1) * 2 + 1]);
        }
        __syncthreads();
        buf ^= 1;
    }

    // ---- epilogue: per-row max over each 16-col group ----------------------
    // acc[mt][nt][0,1]: row = wm*32+mt*16+(lane>>2), cols wn*64+nt*8+(lane&3)*2
    // acc[mt][nt][2,3]: row += 8.  Group g = nt>>1 (16 cols each).
    int mxi[2][2][4];
    #pragma unroll
    for (int mt = 0; mt < 2; mt++)
        #pragma unroll
        for (int hf = 0; hf < 2; hf++)
            #pragma unroll
            for (int g = 0; g < 4; g++) mxi[mt][hf][g] = INT32_MIN;
    #pragma unroll
    for (int mt = 0; mt < 2; mt++)
        #pragma unroll
        for (int nt = 0; nt < 8; nt++) {
            int g = nt >> 1;
            mxi[mt][0][g] = max(mxi[mt][0][g], max(acc[mt][nt][0], acc[mt][nt][1]));
            mxi[mt][1][g] = max(mxi[mt][1][g], max(acc[mt][nt][2], acc[mt][nt][3]));
        }
    #pragma unroll
    for (int off = 1; off <= 2; off <<= 1)
        #pragma unroll
        for (int mt = 0; mt < 2; mt++)
            #pragma unroll
            for (int hf = 0; hf < 2; hf++)
                #pragma unroll
                for (int g = 0; g < 4; g++)
                    mxi[mt][hf][g] = max(mxi[mt][hf][g],
                        __shfl_xor_sync(0xFFFFFFFFu, mxi[mt][hf][g], off));
    if ((lane & 3) == 0) {
        #pragma unroll
        for (int mt = 0; mt < 2; mt++)
            #pragma unroll
            for (int hf = 0; hf < 2; hf++) {
                int r = wm * 32 + mt * 16 + hf * 8 + (lane >> 2);
                #pragma unroll
                for (int g = 0; g < 4; g++)
                    sbm[r][wn * 4 + g] = (float)mxi[mt][hf][g] * (1.0f / 24.0f);
            }
    }
    __syncthreads();
    // 1024 values: [row][c] -> g_blockmax[(b0+row)*NBLK + bx*8 + c]
    #pragma unroll
    for (int p = 0; p < 4; p++) {
        int idx = p * 256 + tid;
        int r = idx >> 3, c = idx & 7;
        g_blockmax[(size_t)(b0 + r) * NBLK + blockIdx.x * 8 + c] = sbm[r][c];
    }
}

// ---------------------------------------------------------------------------
// K3: blockmax scan -> margin-96 candidates (16-head groups) -> exact fp32
//     rescore -> gather. One CTA (256 threads) per batch row. (R4-certified
//     structure, 16-head groups, 2 heads per warp.)
// ---------------------------------------------------------------------------
__global__ __launch_bounds__(256) void argmax_kernel(const float* __restrict__ mem,
                                                     const float* __restrict__ logits,
                                                     float* __restrict__ out) {
    __shared__ __align__(16) float s_row[PROJ];
    __shared__ float wred[8];
    __shared__ float mvs;
    __shared__ int   cand[CAND];
    __shared__ int   ncand;
    __shared__ unsigned long long best;

    const int b = blockIdx.x, tid = threadIdx.x;
    const int lane = tid & 31, wid = tid >> 5;

    if (tid < 64)
        *(float4*)&s_row[tid * 4] = *(const float4*)&g_s[(size_t)b * PROJ + tid * 4];
    if (tid == 0) { ncand = 0; best = 0ull; }

    const float* bmrow = g_blockmax + (size_t)b * NBLK;
    float4 vb = *(const float4*)&bmrow[tid * 4];
    float lm = fmaxf(fmaxf(vb.x, vb.y), fmaxf(vb.z, vb.w));
    #pragma unroll
    for (int o = 16; o >= 1; o >>= 1)
        lm = fmaxf(lm, __shfl_xor_sync(0xFFFFFFFFu, lm, o));
    if (lane == 0) wred[wid] = lm;
    __syncthreads();
    if (tid == 0) {
        float m = wred[0];
        #pragma unroll
        for (int i = 1; i < 8; i++) m = fmaxf(m, wred[i]);
        mvs = m;
    }
    __syncthreads();

    // margin 96 sim units = 15 sigma of int8 screen error (12 sigma needed)
    const float thr = mvs - 96.0f;
    if (vb.x >= thr) { int p = atomicAdd(&ncand, 1); if (p < CAND) cand[p] = tid * 4 + 0; }
    if (vb.y >= thr) { int p = atomicAdd(&ncand, 1); if (p < CAND) cand[p] = tid * 4 + 1; }
    if (vb.z >= thr) { int p = atomicAdd(&ncand, 1); if (p < CAND) cand[p] = tid * 4 + 2; }
    if (vb.w >= thr) { int p = atomicAdd(&ncand, 1); if (p < CAND) cand[p] = tid * 4 + 3; }
    __syncthreads();

    const int nc = min(ncand, CAND);
    const float4 sa = *(const float4*)&s_row[lane * 4];
    const float4 sb = *(const float4*)&s_row[128 + lane * 4];
    for (int c = 0; c < nc; c++) {
        const int hbase = cand[c] * 16;
        #pragma unroll
        for (int t = 0; t < 2; t++) {
            int h = hbase + wid * 2 + t;
            const float4* mr = (const float4*)(mem + (size_t)h * PROJ);
            float4 x = __ldg(&mr[lane]);
            float4 y = __ldg(&mr[lane + 32]);
            float p = x.x * sa.x + x.y * sa.y + x.z * sa.z + x.w * sa.w
                    + y.x * sb.x + y.y * sb.y + y.z * sb.z + y.w * sb.w;
            #pragma unroll
            for (int o = 16; o >= 1; o >>= 1)
                p += __shfl_xor_sync(0xFFFFFFFFu, p, o);
            if (lane == 0) {
                unsigned long long pk =
                    ((unsigned long long)okey(p) << 32) |
                    (unsigned long long)(0xFFFFFFFFu - (unsigned)h);
                atomicMax(&best, pk);
            }
        }
    }
    __syncthreads();
    unsigned h = 0xFFFFFFFFu - (unsigned)(best & 0xFFFFFFFFull);
    if (tid < ACT)
        out[(size_t)b * ACT + tid] = logits[(size_t)h * ACT + tid];
}

// ---------------------------------------------------------------------------
extern "C" void kernel_launch(void* const* d_in, const int* in_sizes, int n_in,
                              void* d_out, int out_size) {
    const float* state  = (const float*)d_in[0];   // [2048,512]
    const float* rp     = (const float*)d_in[1];   // [512,256]
    const float* mems   = (const float*)d_in[2];   // [16384,256]
    const float* logits = (const float*)d_in[3];   // [16384,64]
    float* out = (float*)d_out;                    // [2048,64]

    conv_mem_kernel<<<HEADS * PROJ / (256 * 8), 256>>>(mems);
    proj_kernel<<<dim3(PROJ / 64, BATCH / 64), 256>>>(state, rp);
    sim_mma_kernel<<<dim3(HEADS / 128, BATCH / 128), 256>>>();
    argmax_kernel<<<BATCH, 256>>>(mems, logits, out);
}

// round 14
// speedup vs baseline: 1.4706x; 1.4706x over previous
#include <cuda_runtime.h>
#include <cuda_fp16.h>
#include <cstdint>

#define BATCH   2048
#define FLAT_IN 512
#define PROJ    256
#define HEADS   16384
#define ACT     64
#define NBLK    (HEADS / 32)          // 512 32-head blocks per row

// ---------------- scratch (__device__ globals; allocs are forbidden) -------
__device__ float   g_s[BATCH * PROJ];          // projected state fp32
__device__ __half  g_s_h[BATCH * PROJ];        // projected state fp16
__device__ __half  g_mem_h[HEADS * PROJ];      // memories fp16
__device__ float   g_blockmax[BATCH * NBLK];   // per-row per-32-head max

// ---------------- helpers ---------------------------------------------------
__device__ __forceinline__ uint32_t smem_u32(const void* p) {
    uint32_t a;
    asm("{ .reg .u64 t; cvta.to.shared.u64 t, %1; cvt.u32.u64 %0, t; }"
        : "=r"(a) : "l"(p));
    return a;
}
__device__ __forceinline__ unsigned okey(float f) {
    unsigned u = __float_as_uint(f);
    return (u & 0x80000000u) ? ~u : (u | 0x80000000u);
}

#define LDSM4(d, addr)                                                         \
    asm volatile("ldmatrix.sync.aligned.m8n8.x4.shared.b16 {%0,%1,%2,%3}, [%4];" \
        : "=r"((d)[0]), "=r"((d)[1]), "=r"((d)[2]), "=r"((d)[3]) : "r"(addr))

// all-fp16 HMMA: D,C are 2 regs of f16x2 (row r cols c,c+1 | row r+8 cols c,c+1)
#define MMA_F16(c01, c23, a, br0, br1)                                         \
    asm volatile("mma.sync.aligned.m16n8k16.row.col.f16.f16.f16.f16 "          \
        "{%0,%1}, {%2,%3,%4,%5}, {%6,%7}, {%0,%1};"                            \
        : "+r"(c01), "+r"(c23)                                                 \
        : "r"((a)[0]), "r"((a)[1]), "r"((a)[2]), "r"((a)[3]),                  \
          "r"(br0), "r"(br1))

// ---------------------------------------------------------------------------
// K0: memories fp32 -> fp16  (8 elems / thread)
// ---------------------------------------------------------------------------
__global__ __launch_bounds__(256) void conv_mem_kernel(const float* __restrict__ mem) {
    size_t i = ((size_t)blockIdx.x * 256 + threadIdx.x) * 8;
    float4 a = *(const float4*)&mem[i];
    float4 b = *(const float4*)&mem[i + 4];
    __half2 h[4];
    h[0] = __floats2half2_rn(a.x, a.y);
    h[1] = __floats2half2_rn(a.z, a.w);
    h[2] = __floats2half2_rn(b.x, b.y);
    h[3] = __floats2half2_rn(b.z, b.w);
    *(uint4*)&g_mem_h[i] = *(uint4*)h;
}

// ---------------------------------------------------------------------------
// K1: s = state @ rp   [2048,512]x[512,256], fp32; writes fp32 + fp16 copies
//     (R4-certified structure, plain FFMA)
// ---------------------------------------------------------------------------
__global__ __launch_bounds__(256) void proj_kernel(const float* __restrict__ state,
                                                   const float* __restrict__ rp) {
    __shared__ __align__(16) float As[64 * 36];
    __shared__ __align__(16) float Bs[32 * 68];
    const int tid = threadIdx.x;
    const int tx = tid & 15, ty = tid >> 4;
    const int n0 = blockIdx.x * 64;
    const int b0 = blockIdx.y * 64;
    float acc[4][4] = {};

    for (int kt = 0; kt < FLAT_IN; kt += 32) {
        #pragma unroll
        for (int p = 0; p < 2; p++) {
            int idx = p * 256 + tid;
            int r = idx >> 3, c4 = idx & 7;
            *(float4*)&As[r * 36 + c4 * 4] =
                *(const float4*)&state[(size_t)(b0 + r) * FLAT_IN + kt + c4 * 4];
        }
        #pragma unroll
        for (int p = 0; p < 2; p++) {
            int idx = p * 256 + tid;
            int r = idx >> 4, c4 = idx & 15;
            *(float4*)&Bs[r * 68 + c4 * 4] =
                *(const float4*)&rp[(size_t)(kt + r) * PROJ + n0 + c4 * 4];
        }
        __syncthreads();
        #pragma unroll
        for (int k = 0; k < 32; k++) {
            float4 b4 = *(const float4*)&Bs[k * 68 + tx * 4];
            #pragma unroll
            for (int i = 0; i < 4; i++) {
                float a = As[(ty * 4 + i) * 36 + k];
                acc[i][0] += a * b4.x;  acc[i][1] += a * b4.y;
                acc[i][2] += a * b4.z;  acc[i][3] += a * b4.w;
            }
        }
        __syncthreads();
    }
    #pragma unroll
    for (int i = 0; i < 4; i++) {
        size_t o = (size_t)(b0 + ty * 4 + i) * PROJ + n0 + tx * 4;
        *(float4*)&g_s[o] = make_float4(acc[i][0], acc[i][1], acc[i][2], acc[i][3]);
        __half2 h0 = __floats2half2_rn(acc[i][0], acc[i][1]);
        __half2 h1 = __floats2half2_rn(acc[i][2], acc[i][3]);
        uint2 u;
        u.x = *(uint32_t*)&h0;
        u.y = *(uint32_t*)&h1;
        *(uint2*)&g_s_h[o] = u;
    }
}

// ---------------------------------------------------------------------------
// K2: sims = s_h @ mem_h^T via HMMA m16n8k16 fp16 inputs + FP16 ACCUMULATE.
//     R4-certified loop structure (BM=BN=128, BK=32, 8 warps, stride-40 rows,
//     double buffer, two syncs); epilogue emits per-32-head fp32 maxima.
// ---------------------------------------------------------------------------
__global__ __launch_bounds__(256) void sim_mma_kernel() {
    __shared__ __align__(16) __half As[2][128 * 40];
    __shared__ __align__(16) __half Bs[2][128 * 40];
    __shared__ float sbm[128][4];   // [row][wn*2 + sub], sub = 32-col half

    const int tid  = threadIdx.x;
    const int lane = tid & 31, wid = tid >> 5;
    const int wm = wid & 3, wn = wid >> 2;
    const int h0 = blockIdx.x * 128, b0 = blockIdx.y * 128;

    const __half* Ag = g_s_h   + (size_t)b0 * PROJ;
    const __half* Bg = g_mem_h + (size_t)h0 * PROJ;

    const int r0 = tid >> 2,        c0 = tid & 3;
    const int r1 = 64 + (tid >> 2), c1 = tid & 3;

    uint4 ra0, ra1, rb0, rb1;
    #define GLOAD(kt)                                                          \
        ra0 = *(const uint4*)(Ag + (size_t)r0 * PROJ + (kt) * 32 + c0 * 8);    \
        ra1 = *(const uint4*)(Ag + (size_t)r1 * PROJ + (kt) * 32 + c1 * 8);    \
        rb0 = *(const uint4*)(Bg + (size_t)r0 * PROJ + (kt) * 32 + c0 * 8);    \
        rb1 = *(const uint4*)(Bg + (size_t)r1 * PROJ + (kt) * 32 + c1 * 8)

    // f16x2 accumulators: [mt][nt][0]=rows r cols c,c+1 ; [1]=rows r+8
    uint32_t acc[2][8][2];
    #pragma unroll
    for (int mt = 0; mt < 2; mt++)
        #pragma unroll
        for (int nt = 0; nt < 8; nt++) { acc[mt][nt][0] = 0u; acc[mt][nt][1] = 0u; }

    const uint32_t a_smem = smem_u32(As);
    const uint32_t b_smem = smem_u32(Bs);
    const uint32_t a_row = wm * 32 + (lane & 15);
    const uint32_t a_col = (lane >> 4) * 8;
    const uint32_t b_row = wn * 64 + (lane & 7) + ((lane >> 4) << 3);
    const uint32_t b_col = ((lane >> 3) & 1) * 8;

    GLOAD(0);
    int buf = 0;
    for (int kt = 0; kt < PROJ / 32; kt++) {
        *(uint4*)&As[buf][r0 * 40 + c0 * 8] = ra0;
        *(uint4*)&As[buf][r1 * 40 + c1 * 8] = ra1;
        *(uint4*)&Bs[buf][r0 * 40 + c0 * 8] = rb0;
        *(uint4*)&Bs[buf][r1 * 40 + c1 * 8] = rb1;
        __syncthreads();
        if (kt + 1 < PROJ / 32) { GLOAD(kt + 1); }

        const uint32_t ab = a_smem + (uint32_t)buf * (128 * 40 * 2);
        const uint32_t bb = b_smem + (uint32_t)buf * (128 * 40 * 2);
        #pragma unroll
        for (int ks = 0; ks < 2; ks++) {
            uint32_t af[2][4], bf[4][4];
            #pragma unroll
            for (int mt = 0; mt < 2; mt++)
                LDSM4(af[mt], ab + ((a_row + mt * 16) * 40 + ks * 16 + a_col) * 2);
            #pragma unroll
            for (int np = 0; np < 4; np++)
                LDSM4(bf[np], bb + ((b_row + np * 16) * 40 + ks * 16 + b_col) * 2);
            #pragma unroll
            for (int mt = 0; mt < 2; mt++)
                #pragma unroll
                for (int nt = 0; nt < 8; nt++)
                    MMA_F16(acc[mt][nt][0], acc[mt][nt][1], af[mt],
                            bf[nt >> 1][(nt & 1) * 2], bf[nt >> 1][(nt & 1) * 2 + 1]);
        }
        __syncthreads();
        buf ^= 1;
    }

    // ---- epilogue: per-row max over each 32-col sub-block ------------------
    float mx[2][2][2];   // [mt][half(row r / r+8)][sub]
    #pragma unroll
    for (int mt = 0; mt < 2; mt++)
        #pragma unroll
        for (int hf = 0; hf < 2; hf++)
            #pragma unroll
            for (int sb = 0; sb < 2; sb++) mx[mt][hf][sb] = -1e30f;
    #pragma unroll
    for (int mt = 0; mt < 2; mt++)
        #pragma unroll
        for (int nt = 0; nt < 8; nt++) {
            int sb = nt >> 2;
            #pragma unroll
            for (int hf = 0; hf < 2; hf++) {
                __half2 hv = *(__half2*)&acc[mt][nt][hf];
                float f0 = __half2float(__low2half(hv));
                float f1 = __half2float(__high2half(hv));
                mx[mt][hf][sb] = fmaxf(mx[mt][hf][sb], fmaxf(f0, f1));
            }
        }
    #pragma unroll
    for (int off = 1; off <= 2; off <<= 1)
        #pragma unroll
        for (int mt = 0; mt < 2; mt++)
            #pragma unroll
            for (int hf = 0; hf < 2; hf++)
                #pragma unroll
                for (int sb = 0; sb < 2; sb++)
                    mx[mt][hf][sb] = fmaxf(mx[mt][hf][sb],
                        __shfl_xor_sync(0xFFFFFFFFu, mx[mt][hf][sb], off));
    if ((lane & 3) == 0) {
        #pragma unroll
        for (int mt = 0; mt < 2; mt++)
            #pragma unroll
            for (int hf = 0; hf < 2; hf++) {
                int r = wm * 32 + mt * 16 + hf * 8 + (lane >> 2);
                sbm[r][wn * 2 + 0] = mx[mt][hf][0];
                sbm[r][wn * 2 + 1] = mx[mt][hf][1];
            }
    }
    __syncthreads();
    #pragma unroll
    for (int p = 0; p < 2; p++) {
        int idx = p * 256 + tid;
        int r = idx >> 2, c = idx & 3;
        g_blockmax[(size_t)(b0 + r) * NBLK + blockIdx.x * 4 + c] = sbm[r][c];
    }
}

// ---------------------------------------------------------------------------
// K3: per-row: blockmax scan -> margin candidates -> exact fp32 rescore ->
//     gather. One CTA (256 threads) per batch row.  (R4-certified; margin 40)
// ---------------------------------------------------------------------------
__global__ __launch_bounds__(256) void argmax_kernel(const float* __restrict__ mem,
                                                     const float* __restrict__ logits,
                                                     float* __restrict__ out) {
    __shared__ __align__(16) float s_row[PROJ];
    __shared__ float wred[8];
    __shared__ float mvs;
    __shared__ int   cand[24];
    __shared__ int   ncand;
    __shared__ unsigned long long best;

    const int b = blockIdx.x, tid = threadIdx.x;
    const int lane = tid & 31, wid = tid >> 5;

    if (tid < 64)
        *(float4*)&s_row[tid * 4] = *(const float4*)&g_s[(size_t)b * PROJ + tid * 4];
    if (tid == 0) { ncand = 0; best = 0ull; }

    const float* bmrow = g_blockmax + (size_t)b * NBLK;
    float v0 = bmrow[tid], v1 = bmrow[256 + tid];
    float lm = fmaxf(v0, v1);
    #pragma unroll
    for (int o = 16; o >= 1; o >>= 1)
        lm = fmaxf(lm, __shfl_xor_sync(0xFFFFFFFFu, lm, o));
    if (lane == 0) wred[wid] = lm;
    __syncthreads();
    if (tid == 0) {
        float m = wred[0];
        #pragma unroll
        for (int i = 1; i < 8; i++) m = fmaxf(m, wred[i]);
        mvs = m;
    }
    __syncthreads();

    // margin 40 = 13 sigma of fp16-input/fp16-accum screen error (sigma~3)
    const float thr = mvs - 40.0f;
    if (v0 >= thr) { int p = atomicAdd(&ncand, 1); if (p < 24) cand[p] = tid; }
    if (v1 >= thr) { int p = atomicAdd(&ncand, 1); if (p < 24) cand[p] = 256 + tid; }
    __syncthreads();

    const int nc = min(ncand, 24);
    const float4 sa = *(const float4*)&s_row[lane * 4];
    const float4 sb = *(const float4*)&s_row[128 + lane * 4];
    for (int c = 0; c < nc; c++) {
        const int hbase = cand[c] * 32;
        #pragma unroll
        for (int t = 0; t < 4; t++) {
            int h = hbase + wid * 4 + t;
            const float4* mr = (const float4*)(mem + (size_t)h * PROJ);
            float4 x = __ldg(&mr[lane]);
            float4 y = __ldg(&mr[lane + 32]);
            float p = x.x * sa.x + x.y * sa.y + x.z * sa.z + x.w * sa.w
                    + y.x * sb.x + y.y * sb.y + y.z * sb.z + y.w * sb.w;
            #pragma unroll
            for (int o = 16; o >= 1; o >>= 1)
                p += __shfl_xor_sync(0xFFFFFFFFu, p, o);
            if (lane == 0) {
                unsigned long long pk =
                    ((unsigned long long)okey(p) << 32) |
                    (unsigned long long)(0xFFFFFFFFu - (unsigned)h);
                atomicMax(&best, pk);
            }
        }
    }
    __syncthreads();
    unsigned h = 0xFFFFFFFFu - (unsigned)(best & 0xFFFFFFFFull);
    if (tid < ACT)
        out[(size_t)b * ACT + tid] = logits[(size_t)h * ACT + tid];
}

// ---------------------------------------------------------------------------
extern "C" void kernel_launch(void* const* d_in, const int* in_sizes, int n_in,
                              void* d_out, int out_size) {
    const float* state  = (const float*)d_in[0];   // [2048,512]
    const float* rp     = (const float*)d_in[1];   // [512,256]
    const float* mems   = (const float*)d_in[2];   // [16384,256]
    const float* logits = (const float*)d_in[3];   // [16384,64]
    float* out = (float*)d_out;                    // [2048,64]

    conv_mem_kernel<<<HEADS * PROJ / (256 * 8), 256>>>(mems);
    proj_kernel<<<dim3(PROJ / 64, BATCH / 64), 256>>>(state, rp);
    sim_mma_kernel<<<dim3(HEADS / 128, BATCH / 128), 256>>>();
    argmax_kernel<<<BATCH, 256>>>(mems, logits, out);
}